// round 2
// baseline (speedup 1.0000x reference)
#include <cuda_runtime.h>
#include <cstdint>

#define HID 512
#define H6  3072
#define BB  16
#define TT  1000
#define DTC 0.01f
#define NCTA 129
#define NTHR 256

#define W_TOT 2621440
// output layout (floats): out | hn_last | rnn_out | x_last | x_out
#define OUT_OFF   0ULL
#define HN_OFF    16000ULL
#define RNN_OFF   65152ULL
#define XLAST_OFF 49217152ULL
#define XOUT_OFF  49266304ULL

// -------- persistent device state (allowed: __device__ globals) ----------
__device__ __align__(16) float g_Wt[W_TOT];        // packed effective W, per region: [Kcat][512] (k-major)
__device__ __align__(16) float g_h[2][H6 * BB];    // h double buffer, layout [j][b]
__device__ float g_v[HID];                         // relu(fc1[alm]) @ relu(fc2)
__device__ unsigned g_count;
__device__ volatile unsigned g_epoch;

__device__ __constant__ int c_NC[6]   = {38, 13, 13, 26, 13, 26};
__device__ __constant__ int c_K[6]    = {1536, 512, 512, 1024, 512, 1024};
__device__ __constant__ int c_ROFF[6] = {0, 786432, 1048576, 1310720, 1835008, 2097152};

__device__ __forceinline__ int src_of(int r, int seg) {
    if (r == 0) return seg == 0 ? 0 : (seg == 1 ? 4 : 5);
    if (r == 1) return 0;
    if (r == 2) return 1;
    if (r == 3) return seg == 0 ? 0 : 2;
    if (r == 4) return 3;
    return seg == 0 ? 4 : 5;
}

// ---------------- prep: build W_eff, init h0, v, reset sync --------------
__global__ void prep_kernel(
    const float* __restrict__ hn,
    const float* __restrict__ thal2alm_w, const float* __restrict__ thal2str_w,
    const float* __restrict__ alm2alm_w,  const float* __restrict__ alm2str_w,
    const float* __restrict__ str2snr_w,  const float* __restrict__ str2gpe_w,
    const float* __restrict__ gpe2stn_w,  const float* __restrict__ stn2snr_w,
    const float* __restrict__ snr2thal_w, const float* __restrict__ fc1,
    const float* __restrict__ fc2,        const float* __restrict__ str2str_fixed)
{
    int idx = blockIdx.x * blockDim.x + threadIdx.x;
    if (idx == 0) { g_count = 0; g_epoch = 0; }
    if (idx < W_TOT) {
        int r;
        if (idx < 786432) r = 0;
        else if (idx < 1048576) r = 1;
        else if (idx < 1310720) r = 2;
        else if (idx < 1835008) r = 3;
        else if (idx < 2097152) r = 4;
        else r = 5;
        int rem  = idx - c_ROFF[r];
        int kcat = rem >> 9;        // within-region concatenated source col
        int j    = rem & 511;       // output row within region
        int seg  = kcat >> 9;
        int k    = kcat & 511;
        int wi = j * HID + k;       // raw weight [row j][col k]
        float val;
        if (r == 0) {
            if (seg == 0)      val = -str2str_fixed[wi];                                       // str2str = -fixed
            else if (seg == 1) val = (j >= 128 && j < 384) ? fmaxf(thal2str_w[wi], 0.f) : 0.f; // thal2str row mask
            else               val = (k < 359) ? fmaxf(alm2str_w[wi], 0.f) : 0.f;              // alm2str col mask
        } else if (r == 1) {
            val = (k >= 256) ? -fmaxf(str2gpe_w[wi], 0.f) : 0.f;
        } else if (r == 2) {
            val = -fmaxf(gpe2stn_w[wi], 0.f);
        } else if (r == 3) {
            val = (seg == 0) ? ((k < 256) ? -fmaxf(str2snr_w[wi], 0.f) : 0.f)
                             : fmaxf(stn2snr_w[wi], 0.f);
        } else if (r == 4) {
            val = -fmaxf(snr2thal_w[wi], 0.f);
        } else {
            val = (seg == 0) ? fmaxf(thal2alm_w[wi], 0.f)
                             : fmaxf(alm2alm_w[wi], 0.f) * ((k < 359) ? 1.f : -1.f); // alm_d col sign
        }
        g_Wt[idx] = val;
    } else if (idx < W_TOT + H6 * BB) {
        int e = idx - W_TOT;
        int j = e >> 4, b = e & 15;
        g_h[0][e] = hn[b * H6 + j];   // transpose hn[0] -> [j][b]
    } else if (idx < W_TOT + H6 * BB + HID) {
        int j = idx - (W_TOT + H6 * BB);
        const float* f1 = fc1 + (size_t)(5 * HID + j) * HID;
        float s = 0.f;
        for (int m = 0; m < HID; m++) s += fmaxf(f1[m], 0.f) * fmaxf(fc2[m], 0.f);
        g_v[j] = s;
    }
}

// ---------------- persistent recurrence kernel ---------------------------
__global__ void __launch_bounds__(NTHR, 1) rnn_persist(
    const float* __restrict__ inp,      // [B,T,4]
    const float* __restrict__ inhib,    // [B,6h]
    const float* __restrict__ inp_w,    // [4,6h]
    float* __restrict__ d_out)
{
    extern __shared__ float sm[];
    const int tid = threadIdx.x;

    // ---- CTA -> (region, row range) ----
    int r = 0, c = blockIdx.x;
    while (c >= c_NC[r]) { c -= c_NC[r]; r++; }
    const int N   = c_NC[r];
    const int K   = c_K[r];
    const int bse = HID / N;
    const int rm  = HID - bse * N;
    const int R   = bse + (c < rm ? 1 : 0);
    const int j0  = c * bse + (c < rm ? c : rm);
    int S = NTHR / (4 * R); if (S < 1) S = 1; if (S > 4) S = 4;

    float* sWt  = sm;                 // K*R  (k-major: [k][jj])
    float* sH   = sWt + K * R;        // K*16
    float* sWi  = sH  + K * 16;       // R*4  (relu(inp_w)*strthal)
    float* sInh = sWi + R * 4;        // R*16
    float* sRed = sInh + R * 16;      // S*R*16

    // ---- one-time SMEM fills ----
    const int roff = c_ROFF[r];
    for (int i = tid; i < K * R; i += NTHR) {
        int k = i / R; int jj = i - k * R;
        sWt[i] = g_Wt[roff + (k << 9) + j0 + jj];
    }
    for (int i = tid; i < R * 4; i += NTHR) {
        int jj = i >> 2, ii = i & 3;
        int jg = r * HID + j0 + jj;
        float st = (jg >= 128 && jg < 384) ? 1.f : 0.f;   // strthal
        sWi[i] = fmaxf(inp_w[ii * H6 + jg], 0.f) * st;
    }
    for (int i = tid; i < R * 16; i += NTHR) {
        int jj = i >> 4, b = i & 15;
        sInh[i] = inhib[b * H6 + (r * HID + j0 + jj)];
    }
    const float tonic_r = (r == 1 || r == 2 || r == 4) ? 1.f : 0.f;
    __syncthreads();

    // ---- thread roles ----
    const int b4   = tid & 3;
    const int rest = tid >> 2;
    const int jt   = rest % R;
    const int s    = rest / R;
    const bool active = rest < R * S;
    const int k_lo = active ? (s * K) / S : 0;
    const int k_hi = active ? ((s + 1) * K) / S : 0;
    const int jg   = r * HID + j0 + jt;

    float4* sH4 = (float4*)sH;
    int p = 0;
    for (int t = 0; t < TT; t++) {
        // stage h (L2-coherent loads: other SMs wrote via .cg)
        const float4* hb = (const float4*)(g_h[p]);
        for (int i = tid; i < K * 4; i += NTHR) {
            int k = i >> 2, bq = i & 3;
            int seg = k >> 9, kl = k & 511;
            int src = src_of(r, seg);
            sH4[i] = __ldcg(hb + ((src << 9) + kl) * 4 + bq);
        }
        __syncthreads();

        float4 acc = make_float4(0.f, 0.f, 0.f, 0.f);
        if (active) {
            const float*  pw = sWt + k_lo * R + jt;
            const float4* ph = sH4 + k_lo * 4 + b4;
            #pragma unroll 4
            for (int k = k_lo; k < k_hi; k++) {
                float w = *pw; float4 h4 = *ph;
                acc.x = fmaf(w, h4.x, acc.x);
                acc.y = fmaf(w, h4.y, acc.y);
                acc.z = fmaf(w, h4.z, acc.z);
                acc.w = fmaf(w, h4.w, acc.w);
                pw += R; ph += 4;
            }
        }
        if (S > 1) {                       // K-split partial reduction
            if (active && s > 0)
                ((float4*)sRed)[((s - 1) * R + jt) * 4 + b4] = acc;
            __syncthreads();
            if (active && s == 0) {
                for (int ss = 0; ss < S - 1; ss++) {
                    float4 o = ((float4*)sRed)[(ss * R + jt) * 4 + b4];
                    acc.x += o.x; acc.y += o.y; acc.z += o.z; acc.w += o.w;
                }
            }
        }
        if (active && s == 0) {            // update + store
            float4 hold = __ldcg((const float4*)(g_h[p]) + jg * 4 + b4);
            float4 hnew;
            const float w0 = sWi[jt * 4 + 0], w1 = sWi[jt * 4 + 1];
            const float w2 = sWi[jt * 4 + 2], w3 = sWi[jt * 4 + 3];
            float* ha = &hold.x; float* aa = &acc.x; float* na = &hnew.x;
            #pragma unroll
            for (int i2 = 0; i2 < 4; i2++) {
                int b = b4 * 4 + i2;
                float4 ip = *(const float4*)(inp + (size_t)(b * TT + t) * 4);
                float dot = w0 * ip.x + w1 * ip.y + w2 * ip.z + w3 * ip.w;
                float d   = dot + sInh[jt * 16 + b] + tonic_r;
                float v = ha[i2] * (1.f - DTC) + DTC * (aa[i2] + d);
                v = fmaxf(v, 0.f);
                na[i2] = v;
                d_out[RNN_OFF + (size_t)(b * TT + t) * H6 + jg] = v;
                if (t == TT - 1) d_out[HN_OFF + (size_t)b * H6 + jg] = v;
            }
            __stcg((float4*)(g_h[p ^ 1]) + jg * 4 + b4, hnew);
        }

        // ---- software grid barrier (all 129 CTAs resident, 1/SM) ----
        __syncthreads();
        if (tid == 0) {
            __threadfence();
            unsigned target = (unsigned)(t + 1);
            if (atomicAdd(&g_count, 1u) == NCTA - 1) {
                atomicExch(&g_count, 0u);
                __threadfence();
                g_epoch = target;
            } else {
                while (g_epoch < target) { __nanosleep(64); }
            }
            __threadfence();
        }
        __syncthreads();
        p ^= 1;
    }
}

// ---------------- epilogue: out = sigmoid(alm_h . v) ---------------------
__global__ void out_kernel(float* __restrict__ d_out)
{
    int gw   = (blockIdx.x * blockDim.x + threadIdx.x) >> 5;
    int lane = threadIdx.x & 31;
    if (gw >= BB * TT) return;
    const float* row = d_out + RNN_OFF + (size_t)gw * H6 + 5 * HID;
    float sum = 0.f;
    for (int j = lane; j < HID; j += 32) sum = fmaf(row[j], g_v[j], sum);
    #pragma unroll
    for (int o = 16; o; o >>= 1) sum += __shfl_xor_sync(0xffffffffu, sum, o);
    if (lane == 0) d_out[gw] = 1.f / (1.f + expf(-sum));
}

// ---------------- epilogue: x_out / x_last broadcast copy ----------------
__global__ void x_kernel(const float* __restrict__ x, float* __restrict__ d_out)
{
    const float4* x4 = (const float4*)x;
    float4* o4 = (float4*)d_out;
    const size_t total = 12288 + 12288000;  // x_last f4 + x_out f4
    for (size_t i = blockIdx.x * (size_t)blockDim.x + threadIdx.x; i < total;
         i += (size_t)gridDim.x * blockDim.x) {
        if (i < 12288) {
            o4[XLAST_OFF / 4 + i] = x4[i];
        } else {
            size_t e = i - 12288;
            int j4 = (int)(e % 768);
            int bt = (int)(e / 768);
            int b  = bt / TT;
            o4[XOUT_OFF / 4 + e] = x4[b * 768 + j4];
        }
    }
}

extern "C" void kernel_launch(void* const* d_in, const int* in_sizes, int n_in,
                              void* d_out_v, int out_size)
{
    const float* inp        = (const float*)d_in[0];
    const float* hn         = (const float*)d_in[1];
    const float* x          = (const float*)d_in[2];
    const float* inhib      = (const float*)d_in[3];
    /* d_in[4] str2str_w unused: str2str block is -str2str_fixed */
    const float* thal2alm_w = (const float*)d_in[5];
    const float* thal2str_w = (const float*)d_in[6];
    const float* alm2alm_w  = (const float*)d_in[7];
    const float* alm2str_w  = (const float*)d_in[8];
    const float* str2snr_w  = (const float*)d_in[9];
    const float* str2gpe_w  = (const float*)d_in[10];
    const float* gpe2stn_w  = (const float*)d_in[11];
    const float* stn2snr_w  = (const float*)d_in[12];
    const float* snr2thal_w = (const float*)d_in[13];
    const float* inp_w      = (const float*)d_in[14];
    const float* fc1        = (const float*)d_in[15];
    const float* fc2        = (const float*)d_in[16];
    const float* fixed      = (const float*)d_in[17];
    float* d_out = (float*)d_out_v;

    cudaFuncSetAttribute(rnn_persist, cudaFuncAttributeMaxDynamicSharedMemorySize, 196608);

    int prep_total = W_TOT + H6 * BB + HID;
    prep_kernel<<<(prep_total + NTHR - 1) / NTHR, NTHR>>>(
        hn, thal2alm_w, thal2str_w, alm2alm_w, alm2str_w, str2snr_w,
        str2gpe_w, gpe2stn_w, stn2snr_w, snr2thal_w, fc1, fc2, fixed);

    rnn_persist<<<NCTA, NTHR, 192 * 1024>>>(inp, inhib, inp_w, d_out);

    out_kernel<<<(BB * TT * 32 + NTHR - 1) / NTHR, NTHR>>>(d_out);
    x_kernel<<<4096, NTHR>>>(x, d_out);
}

// round 4
// speedup vs baseline: 2.2239x; 2.2239x over previous
#include <cuda_runtime.h>
#include <cstdint>

#define HID 512
#define H6  3072
#define BB  16
#define TT  1000
#define DTC 0.01f
#define NTHR 256
#define NCTA 145

#define W_TOT 2621440
// output layout (floats): out | hn_last | rnn_out | x_last | x_out
#define OUT_OFF   0ULL
#define HN_OFF    16000ULL
#define RNN_OFF   65152ULL
#define XLAST_OFF 49217152ULL
#define XOUT_OFF  49266304ULL

// -------- persistent device state ----------
__device__ __align__(16) float g_Wt[W_TOT];      // packed effective W, per region [Kcat][512]
__device__ __align__(16) float g_h[8][H6 * BB];  // h ring buffer, layout [j][b]
__device__ float g_v[HID];                       // relu(fc1[alm]) @ relu(fc2)
__device__ unsigned g_cnt[6];                    // per-region monotonic step counters

__host__ __device__ constexpr int roff_of(int r) {
    return r==0?0 : r==1?786432 : r==2?1048576 : r==3?1310720 : r==4?1835008 : 2097152;
}
__host__ __device__ constexpr unsigned ncta_of(int r) {
    return r==0?43u : (r==3||r==5)?27u : 16u;
}

// ---------------- PTX helpers ----------------
__device__ __forceinline__ void cp16(unsigned dst_s, const void* src) {
    asm volatile("cp.async.cg.shared.global [%0], [%1], 16;" :: "r"(dst_s), "l"(src) : "memory");
}
__device__ __forceinline__ void cp_wait() {
    asm volatile("cp.async.commit_group;\ncp.async.wait_group 0;" ::: "memory");
}
__device__ __forceinline__ unsigned ld_acq(const unsigned* p) {
    unsigned v;
    asm volatile("ld.acquire.gpu.global.u32 %0, [%1];" : "=r"(v) : "l"(p) : "memory");
    return v;
}
__device__ __forceinline__ void red_rel(unsigned* p) {
    asm volatile("red.release.gpu.global.add.u32 [%0], %1;" :: "l"(p), "r"(1u) : "memory");
}
#define FMA2(acc, w, h) asm("fma.rn.f32x2 %0, %1, %2, %0;" : "+l"(acc) : "l"(w), "l"(h))
#define ADD2(acc, v)    asm("add.rn.f32x2 %0, %0, %1;"     : "+l"(acc) : "l"(v))
#define PACK2(d, f)     asm("mov.b64 %0, {%1, %1};"        : "=l"(d)   : "f"(f))
#define UNPK2(lo, hi, v) asm("mov.b64 {%0, %1}, %2;" : "=f"(lo), "=f"(hi) : "l"(v))

// ---------------- prep: build W_eff, init h0, v, reset counters ----------
__global__ void prep_kernel(
    const float* __restrict__ hn,
    const float* __restrict__ thal2alm_w, const float* __restrict__ thal2str_w,
    const float* __restrict__ alm2alm_w,  const float* __restrict__ alm2str_w,
    const float* __restrict__ str2snr_w,  const float* __restrict__ str2gpe_w,
    const float* __restrict__ gpe2stn_w,  const float* __restrict__ stn2snr_w,
    const float* __restrict__ snr2thal_w, const float* __restrict__ fc1,
    const float* __restrict__ fc2,        const float* __restrict__ str2str_fixed)
{
    int idx = blockIdx.x * blockDim.x + threadIdx.x;
    if (idx < 6) g_cnt[idx] = 0u;
    if (idx < W_TOT) {
        int r;
        if (idx < 786432) r = 0;
        else if (idx < 1048576) r = 1;
        else if (idx < 1310720) r = 2;
        else if (idx < 1835008) r = 3;
        else if (idx < 2097152) r = 4;
        else r = 5;
        int rem  = idx - roff_of(r);
        int kcat = rem >> 9;
        int j    = rem & 511;
        int seg  = kcat >> 9;
        int k    = kcat & 511;
        int wi = j * HID + k;
        float val;
        if (r == 0) {
            if (seg == 0)      val = -str2str_fixed[wi];
            else if (seg == 1) val = (j >= 128 && j < 384) ? fmaxf(thal2str_w[wi], 0.f) : 0.f;
            else               val = (k < 359) ? fmaxf(alm2str_w[wi], 0.f) : 0.f;
        } else if (r == 1) {
            val = (k >= 256) ? -fmaxf(str2gpe_w[wi], 0.f) : 0.f;
        } else if (r == 2) {
            val = -fmaxf(gpe2stn_w[wi], 0.f);
        } else if (r == 3) {
            val = (seg == 0) ? ((k < 256) ? -fmaxf(str2snr_w[wi], 0.f) : 0.f)
                             : fmaxf(stn2snr_w[wi], 0.f);
        } else if (r == 4) {
            val = -fmaxf(snr2thal_w[wi], 0.f);
        } else {
            val = (seg == 0) ? fmaxf(thal2alm_w[wi], 0.f)
                             : fmaxf(alm2alm_w[wi], 0.f) * ((k < 359) ? 1.f : -1.f);
        }
        g_Wt[idx] = val;
    } else if (idx < W_TOT + H6 * BB) {
        int e = idx - W_TOT;
        int j = e >> 4, b = e & 15;
        g_h[0][e] = hn[b * H6 + j];
    } else if (idx < W_TOT + H6 * BB + HID) {
        int j = idx - (W_TOT + H6 * BB);
        const float* f1 = fc1 + (size_t)(5 * HID + j) * HID;
        float s = 0.f;
        for (int m = 0; m < HID; m++) s += fmaxf(f1[m], 0.f) * fmaxf(fc2[m], 0.f);
        g_v[j] = s;
    }
}

// ---------------- persistent recurrence, templated per region ------------
template<int RG, int R, int S, int K, int NSEG, int SA, int SB, int SC>
__device__ __forceinline__ void run_region(
    int c, const float* __restrict__ inp, const float* __restrict__ inhib,
    const float* __restrict__ inp_w, float* __restrict__ d_out, float* sm)
{
    const int tid = threadIdx.x;
    const int j0  = c * R;

    float* sWt  = sm;                      // K*R  [k][jj]
    float* sH   = sWt + K * R;             // K*16 [k][b]
    float* sRed = sH + K * 16;             // S*R*16
    float* sInh = sRed + S * R * 16;       // R*16
    float* sWi  = sInh + R * 16;           // R*4
    float* sInp = sWi + R * 4;             // 64

    // one-time SMEM fills
    for (int i = tid; i < K * R; i += NTHR) {
        int k = i / R, jj = i - k * R;
        int jrow = j0 + jj;
        sWt[i] = (jrow < 512) ? g_Wt[roff_of(RG) + (k << 9) + jrow] : 0.f;
    }
    for (int i = tid; i < R * 16; i += NTHR) {
        int jj = i >> 4, b = i & 15;
        int jrow = j0 + jj;
        sInh[i] = (jrow < 512) ? inhib[b * H6 + RG * HID + jrow] : 0.f;
    }
    for (int i = tid; i < R * 4; i += NTHR) {
        int jj = i >> 2, ii = i & 3;
        int jrow = j0 + jj;
        int jg = RG * HID + jrow;
        float st = (RG == 0 && jrow < 512 && jg >= 128 && jg < 384) ? 1.f : 0.f;
        sWi[i] = st * fmaxf(inp_w[ii * H6 + (jg < H6 ? jg : 0)], 0.f);
    }
    const float tonic = (RG == 1 || RG == 2 || RG == 4) ? 1.f : 0.f;

    const unsigned sHb = (unsigned)__cvta_generic_to_shared(sH);

    const int jt  = tid % R;
    const int s   = tid / R;
    const bool act = (s < S);
    const int k_lo = act ? (s * K) / S : 0;
    const int k_hi = act ? ((s + 1) * K) / S : 0;

    __syncthreads();

    for (int t = 0; t < TT; t++) {
        // ---- wait for source regions to finish step t-1 ----
        if (tid == 0 && t > 0) {
            const unsigned ut = (unsigned)t;
            while (ld_acq(&g_cnt[SA]) < ncta_of(SA) * ut) __nanosleep(40);
            if (NSEG > 1) while (ld_acq(&g_cnt[SB]) < ncta_of(SB) * ut) __nanosleep(40);
            if (NSEG > 2) while (ld_acq(&g_cnt[SC]) < ncta_of(SC) * ut) __nanosleep(40);
        }
        __syncthreads();

        // ---- stage h sources via cp.async (high MLP) ----
        const float* hb = g_h[t & 7];
        #pragma unroll
        for (int seg = 0; seg < NSEG; seg++) {
            const int src = (seg == 0) ? SA : ((seg == 1) ? SB : SC);
            const float4* sp = (const float4*)(hb + src * HID * 16);
            const unsigned dp = sHb + (unsigned)(seg * 2048) * 16u;
            #pragma unroll
            for (int i = 0; i < 8; i++)
                cp16(dp + (unsigned)(i * NTHR + tid) * 16u, sp + i * NTHR + tid);
        }
        if (RG == 0 && tid < 64)
            sInp[tid] = __ldg(inp + (size_t)(tid >> 2) * TT * 4 + t * 4 + (tid & 3));
        cp_wait();
        __syncthreads();

        // ---- partial dot products (f32x2 packed FFMA) ----
        unsigned long long a0 = 0, a1 = 0, a2 = 0, a3 = 0, a4 = 0, a5 = 0, a6 = 0, a7 = 0;
        if (act) {
            const float* pw = sWt + (size_t)k_lo * R + jt;
            const ulonglong2* ph = (const ulonglong2*)sH + (size_t)k_lo * 4;
            #pragma unroll 4
            for (int k = k_lo; k < k_hi; k++) {
                float w = *pw; pw += R;
                unsigned long long ww; PACK2(ww, w);
                ulonglong2 u0 = ph[0], u1 = ph[1], u2 = ph[2], u3 = ph[3]; ph += 4;
                FMA2(a0, ww, u0.x); FMA2(a1, ww, u0.y);
                FMA2(a2, ww, u1.x); FMA2(a3, ww, u1.y);
                FMA2(a4, ww, u2.x); FMA2(a5, ww, u2.y);
                FMA2(a6, ww, u3.x); FMA2(a7, ww, u3.y);
            }
            ulonglong2* rp = (ulonglong2*)sRed + ((size_t)s * R + jt) * 4;
            rp[0] = make_ulonglong2(a0, a1); rp[1] = make_ulonglong2(a2, a3);
            rp[2] = make_ulonglong2(a4, a5); rp[3] = make_ulonglong2(a6, a7);
        }
        __syncthreads();

        // ---- reduce across S + state update (threads: 4 per row) ----
        if (tid < 4 * R) {
            const int jr = tid >> 2, q = tid & 3;
            const int jrow = j0 + jr;
            unsigned long long x = 0, y = 0;
            const ulonglong2* rp = (const ulonglong2*)sRed + (size_t)jr * 4 + q;
            #pragma unroll
            for (int ss = 0; ss < S; ss++) {
                ulonglong2 v = rp[(size_t)ss * R * 4];
                ADD2(x, v.x); ADD2(y, v.y);
            }
            if (jrow < 512) {
                const int jg = RG * HID + jrow;
                float ac[4];
                UNPK2(ac[0], ac[1], x); UNPK2(ac[2], ac[3], y);
                float4 hold = __ldcg((const float4*)(g_h[t & 7] + (size_t)jg * 16) + q);
                float hv[4] = {hold.x, hold.y, hold.z, hold.w};
                float w0 = 0.f, w1 = 0.f, w2 = 0.f, w3 = 0.f;
                if (RG == 0) { w0 = sWi[jr*4]; w1 = sWi[jr*4+1]; w2 = sWi[jr*4+2]; w3 = sWi[jr*4+3]; }
                float4 hnew;
                float* np = &hnew.x;
                #pragma unroll
                for (int i2 = 0; i2 < 4; i2++) {
                    const int b = q * 4 + i2;
                    float d = sInh[jr * 16 + b] + tonic;
                    if (RG == 0)
                        d += w0 * sInp[b*4] + w1 * sInp[b*4+1] + w2 * sInp[b*4+2] + w3 * sInp[b*4+3];
                    float v = hv[i2] * (1.f - DTC) + DTC * (ac[i2] + d);
                    v = fmaxf(v, 0.f);
                    np[i2] = v;
                    d_out[RNN_OFF + ((size_t)b * TT + t) * H6 + jg] = v;
                    if (t == TT - 1) d_out[HN_OFF + (size_t)b * H6 + jg] = v;
                }
                __stcg((float4*)(g_h[(t + 1) & 7] + (size_t)jg * 16) + q, hnew);
            }
        }
        __syncthreads();
        if (tid == 0) red_rel(&g_cnt[RG]);   // publish step t done (release)
    }
}

__global__ void __launch_bounds__(NTHR, 1) rnn_persist(
    const float* __restrict__ inp, const float* __restrict__ inhib,
    const float* __restrict__ inp_w, float* __restrict__ d_out)
{
    extern __shared__ float sm[];
    const int b = blockIdx.x;
    //                 RG  R   S   K    NSEG SA SB SC
    if      (b < 43)  run_region<0, 12, 21, 1536, 3, 0, 4, 5>(b,       inp, inhib, inp_w, d_out, sm);
    else if (b < 59)  run_region<1, 32,  8,  512, 1, 0, 0, 0>(b - 43,  inp, inhib, inp_w, d_out, sm);
    else if (b < 75)  run_region<2, 32,  8,  512, 1, 1, 0, 0>(b - 59,  inp, inhib, inp_w, d_out, sm);
    else if (b < 102) run_region<3, 19, 13, 1024, 2, 0, 2, 0>(b - 75,  inp, inhib, inp_w, d_out, sm);
    else if (b < 118) run_region<4, 32,  8,  512, 1, 3, 0, 0>(b - 102, inp, inhib, inp_w, d_out, sm);
    else              run_region<5, 19, 13, 1024, 2, 4, 5, 0>(b - 118, inp, inhib, inp_w, d_out, sm);
}

// ---------------- epilogue: out = sigmoid(alm_h . v) ---------------------
__global__ void out_kernel(float* __restrict__ d_out)
{
    int gw   = (blockIdx.x * blockDim.x + threadIdx.x) >> 5;
    int lane = threadIdx.x & 31;
    if (gw >= BB * TT) return;
    const float* row = d_out + RNN_OFF + (size_t)gw * H6 + 5 * HID;
    float sum = 0.f;
    for (int j = lane; j < HID; j += 32) sum = fmaf(row[j], g_v[j], sum);
    #pragma unroll
    for (int o = 16; o; o >>= 1) sum += __shfl_xor_sync(0xffffffffu, sum, o);
    if (lane == 0) d_out[gw] = 1.f / (1.f + expf(-sum));
}

// ---------------- epilogue: x_out / x_last broadcast copy ----------------
__global__ void x_kernel(const float* __restrict__ x, float* __restrict__ d_out)
{
    const float4* x4 = (const float4*)x;
    float4* o4 = (float4*)d_out;
    const size_t total = 12288 + 12288000;
    for (size_t i = blockIdx.x * (size_t)blockDim.x + threadIdx.x; i < total;
         i += (size_t)gridDim.x * blockDim.x) {
        if (i < 12288) {
            o4[XLAST_OFF / 4 + i] = x4[i];
        } else {
            size_t e = i - 12288;
            int j4 = (int)(e % 768);
            int bt = (int)(e / 768);
            int bq = bt / TT;
            o4[XOUT_OFF / 4 + e] = x4[bq * 768 + j4];
        }
    }
}

extern "C" void kernel_launch(void* const* d_in, const int* in_sizes, int n_in,
                              void* d_out_v, int out_size)
{
    const float* inp        = (const float*)d_in[0];
    const float* hn         = (const float*)d_in[1];
    const float* x          = (const float*)d_in[2];
    const float* inhib      = (const float*)d_in[3];
    const float* thal2alm_w = (const float*)d_in[5];
    const float* thal2str_w = (const float*)d_in[6];
    const float* alm2alm_w  = (const float*)d_in[7];
    const float* alm2str_w  = (const float*)d_in[8];
    const float* str2snr_w  = (const float*)d_in[9];
    const float* str2gpe_w  = (const float*)d_in[10];
    const float* gpe2stn_w  = (const float*)d_in[11];
    const float* stn2snr_w  = (const float*)d_in[12];
    const float* snr2thal_w = (const float*)d_in[13];
    const float* inp_w      = (const float*)d_in[14];
    const float* fc1        = (const float*)d_in[15];
    const float* fc2        = (const float*)d_in[16];
    const float* fixed      = (const float*)d_in[17];
    float* d_out = (float*)d_out_v;

    // max smem: region 0 = 73728 + 98304 + 16128 + 768 + 192 + 256 = 189376 B
    static int smem_set = 0;
    if (!smem_set) {
        cudaFuncSetAttribute(rnn_persist, cudaFuncAttributeMaxDynamicSharedMemorySize, 190464);
        smem_set = 1;
    }

    int prep_total = W_TOT + H6 * BB + HID;
    prep_kernel<<<(prep_total + NTHR - 1) / NTHR, NTHR>>>(
        hn, thal2alm_w, thal2str_w, alm2alm_w, alm2str_w, str2snr_w,
        str2gpe_w, gpe2stn_w, stn2snr_w, snr2thal_w, fc1, fc2, fixed);

    rnn_persist<<<NCTA, NTHR, 190464>>>(inp, inhib, inp_w, d_out);

    out_kernel<<<(BB * TT * 32 + NTHR - 1) / NTHR, NTHR>>>(d_out);
    x_kernel<<<4096, NTHR>>>(x, d_out);
}

// round 6
// speedup vs baseline: 2.4770x; 1.1138x over previous
#include <cuda_runtime.h>
#include <cstdint>

#define HID 512
#define H6  3072
#define BB  16
#define TT  1000
#define DTC 0.01f
#define NTHR 256
#define NCTA 148

#define W_TOT 2621440
// output layout (floats): out | hn_last | rnn_out | x_last | x_out
#define OUT_OFF   0ULL
#define HN_OFF    16000ULL
#define RNN_OFF   65152ULL
#define XLAST_OFF 49217152ULL
#define XOUT_OFF  49266304ULL

// -------- persistent device state ----------
__device__ __align__(16) float g_Wt[W_TOT];      // packed effective W, per region [Kcat][512]
__device__ __align__(16) float g_h[8][H6 * BB];  // h ring buffer, layout [j][b]
__device__ float g_v[HID];                       // relu(fc1[alm]) @ relu(fc2)
__device__ unsigned g_cnt[6];                    // per-region monotonic step counters

__host__ __device__ constexpr int roff_of(int r) {
    return r==0?0 : r==1?786432 : r==2?1048576 : r==3?1310720 : r==4?1835008 : 2097152;
}
// CTAs per region (for counter targets): str=48, gpe=8, stn=16, snr=28, thal=16, alm=32
__host__ __device__ constexpr unsigned ncta_of(int r) {
    return r==0?48u : r==1?8u : r==2?16u : r==3?28u : r==4?16u : 32u;
}

// ---------------- PTX helpers ----------------
__device__ __forceinline__ void cp16(unsigned dst_s, const void* src) {
    asm volatile("cp.async.cg.shared.global [%0], [%1], 16;" :: "r"(dst_s), "l"(src) : "memory");
}
#define CP_COMMIT() asm volatile("cp.async.commit_group;" ::: "memory")
#define CP_WAIT(N)  asm volatile("cp.async.wait_group %0;" :: "n"(N) : "memory")
__device__ __forceinline__ unsigned ld_acq(const unsigned* p) {
    unsigned v;
    asm volatile("ld.acquire.gpu.global.u32 %0, [%1];" : "=r"(v) : "l"(p) : "memory");
    return v;
}
__device__ __forceinline__ void red_rel(unsigned* p) {
    asm volatile("red.release.gpu.global.add.u32 [%0], %1;" :: "l"(p), "r"(1u) : "memory");
}
#define FMA2(acc, w, h) asm("fma.rn.f32x2 %0, %1, %2, %0;" : "+l"(acc) : "l"(w), "l"(h))
#define ADD2(acc, v)    asm("add.rn.f32x2 %0, %0, %1;"     : "+l"(acc) : "l"(v))
#define PACK2(d, f)     asm("mov.b64 %0, {%1, %1};"        : "=l"(d)   : "f"(f))
#define UNPK2(lo, hi, v) asm("mov.b64 {%0, %1}, %2;" : "=f"(lo), "=f"(hi) : "l"(v))

// ---------------- prep: build W_eff, init h0, v, reset counters ----------
__global__ void prep_kernel(
    const float* __restrict__ hn,
    const float* __restrict__ thal2alm_w, const float* __restrict__ thal2str_w,
    const float* __restrict__ alm2alm_w,  const float* __restrict__ alm2str_w,
    const float* __restrict__ str2snr_w,  const float* __restrict__ str2gpe_w,
    const float* __restrict__ gpe2stn_w,  const float* __restrict__ stn2snr_w,
    const float* __restrict__ snr2thal_w, const float* __restrict__ fc1,
    const float* __restrict__ fc2,        const float* __restrict__ str2str_fixed)
{
    int idx = blockIdx.x * blockDim.x + threadIdx.x;
    if (idx < 6) g_cnt[idx] = 0u;
    if (idx < W_TOT) {
        int r;
        if (idx < 786432) r = 0;
        else if (idx < 1048576) r = 1;
        else if (idx < 1310720) r = 2;
        else if (idx < 1835008) r = 3;
        else if (idx < 2097152) r = 4;
        else r = 5;
        int rem  = idx - roff_of(r);
        int kcat = rem >> 9;
        int j    = rem & 511;
        int seg  = kcat >> 9;
        int k    = kcat & 511;
        int wi = j * HID + k;
        float val;
        if (r == 0) {
            if (seg == 0)      val = -str2str_fixed[wi];
            else if (seg == 1) val = (j >= 128 && j < 384) ? fmaxf(thal2str_w[wi], 0.f) : 0.f;
            else               val = (k < 359) ? fmaxf(alm2str_w[wi], 0.f) : 0.f;
        } else if (r == 1) {
            val = (k >= 256) ? -fmaxf(str2gpe_w[wi], 0.f) : 0.f;
        } else if (r == 2) {
            val = -fmaxf(gpe2stn_w[wi], 0.f);
        } else if (r == 3) {
            val = (seg == 0) ? ((k < 256) ? -fmaxf(str2snr_w[wi], 0.f) : 0.f)
                             : fmaxf(stn2snr_w[wi], 0.f);
        } else if (r == 4) {
            val = -fmaxf(snr2thal_w[wi], 0.f);
        } else {
            val = (seg == 0) ? fmaxf(thal2alm_w[wi], 0.f)
                             : fmaxf(alm2alm_w[wi], 0.f) * ((k < 359) ? 1.f : -1.f);
        }
        g_Wt[idx] = val;
    } else if (idx < W_TOT + H6 * BB) {
        int e = idx - W_TOT;
        int j = e >> 4, b = e & 15;
        g_h[0][e] = hn[b * H6 + j];
    } else if (idx < W_TOT + H6 * BB + HID) {
        int j = idx - (W_TOT + H6 * BB);
        const float* f1 = fc1 + (size_t)(5 * HID + j) * HID;
        float s = 0.f;
        for (int m = 0; m < HID; m++) s += fmaxf(f1[m], 0.f) * fmaxf(fc2[m], 0.f);
        g_v[j] = s;
    }
}

// ---------------- inner dot-product over one segment ---------------------
template<int R>
__device__ __forceinline__ void dot_seg(const float* __restrict__ sWt,
    const ulonglong2* __restrict__ sH2, int jt, int coff, int klo, int khi,
    unsigned long long* a)
{
    const float* pw = sWt + (size_t)(coff + klo) * R + jt;
    const ulonglong2* ph = sH2 + (size_t)(coff + klo) * 4;
    #pragma unroll 4
    for (int k = klo; k < khi; k++) {
        float w = *pw; pw += R;
        unsigned long long ww; PACK2(ww, w);
        ulonglong2 u0 = ph[0], u1 = ph[1], u2 = ph[2], u3 = ph[3]; ph += 4;
        FMA2(a[0], ww, u0.x); FMA2(a[1], ww, u0.y);
        FMA2(a[2], ww, u1.x); FMA2(a[3], ww, u1.y);
        FMA2(a[4], ww, u2.x); FMA2(a[5], ww, u2.y);
        FMA2(a[6], ww, u3.x); FMA2(a[7], ww, u3.y);
    }
}

// ---------------- persistent recurrence, templated per region ------------
// Segments: (SRC region, W orig-kcat offset, L length). h rows = SRC*512 + (W&511) + k
template<int RG, int R, int S, int K, int NSEG,
         int S0, int W0, int L0, int S1, int W1, int L1, int S2, int W2, int L2>
__device__ __forceinline__ void run_region(
    int j0, const float* __restrict__ inp, const float* __restrict__ inhib,
    const float* __restrict__ inp_w, float* __restrict__ d_out, float* sm)
{
    const int tid = threadIdx.x;

    float* sWt  = sm;                      // K*R  [k][jj]
    float* sH   = sWt + K * R;             // K*16 [k][b]
    float* sRed = sH + K * 16;             // S*R*16
    float* sInh = sRed + S * R * 16;       // R*16
    float* sWi  = sInh + R * 16;           // R*4
    float* sInp = sWi + R * 4;             // 64

    // ---- one-time weight fills (per segment, concat layout) ----
    for (int i = tid; i < L0 * R; i += NTHR) {
        int k = i / R, jj = i - k * R; int jrow = j0 + jj;
        sWt[(size_t)k * R + jj] = (jrow < 512) ? g_Wt[roff_of(RG) + ((W0 + k) << 9) + jrow] : 0.f;
    }
    if constexpr (NSEG > 1)
    for (int i = tid; i < L1 * R; i += NTHR) {
        int k = i / R, jj = i - k * R; int jrow = j0 + jj;
        sWt[(size_t)(L0 + k) * R + jj] = (jrow < 512) ? g_Wt[roff_of(RG) + ((W1 + k) << 9) + jrow] : 0.f;
    }
    if constexpr (NSEG > 2)
    for (int i = tid; i < L2 * R; i += NTHR) {
        int k = i / R, jj = i - k * R; int jrow = j0 + jj;
        sWt[(size_t)(L0 + L1 + k) * R + jj] = (jrow < 512) ? g_Wt[roff_of(RG) + ((W2 + k) << 9) + jrow] : 0.f;
    }
    for (int i = tid; i < R * 16; i += NTHR) {
        int jj = i >> 4, b = i & 15; int jrow = j0 + jj;
        sInh[i] = (jrow < 512) ? inhib[b * H6 + RG * HID + jrow] : 0.f;
    }
    for (int i = tid; i < R * 4; i += NTHR) {
        int jj = i >> 2, ii = i & 3; int jrow = j0 + jj;
        int jg = RG * HID + jrow;
        float st = (RG == 0 && jrow < 512 && jg >= 128 && jg < 384) ? 1.f : 0.f;
        sWi[i] = st * fmaxf(inp_w[ii * H6 + (jg < H6 ? jg : 0)], 0.f);
    }
    const float tonic = (RG == 1 || RG == 2 || RG == 4) ? 1.f : 0.f;

    // ---- update-thread identity + h kept in registers ----
    const int jr = tid >> 2, q = tid & 3;
    const int jrow_u = j0 + jr;
    const bool upd = (tid < 4 * R) && (jrow_u < 512);
    const int jg_u = RG * HID + jrow_u;
    float4 hown = make_float4(0.f, 0.f, 0.f, 0.f);
    if (upd) hown = *((const float4*)(g_h[0] + (size_t)jg_u * 16) + q);

    const unsigned sHb = (unsigned)__cvta_generic_to_shared(sH);
    const int jt = tid % R;
    const int s  = tid / R;
    const bool act = s < S;
    const int klo0 = (s * L0) / S,        khi0 = ((s + 1) * L0) / S;
    const int klo1 = (s * L1) / S,        khi1 = ((s + 1) * L1) / S;
    const int klo2 = (s * L2) / S,        khi2 = ((s + 1) * L2) / S;

    __syncthreads();

    for (int t = 0; t < TT; t++) {
        const float* hb = g_h[t & 7];
        const unsigned ut = (unsigned)t;

        // ---- parallel first-read of source counters ----
        unsigned c0 = ld_acq(&g_cnt[S0]);
        unsigned c1 = (NSEG > 1) ? ld_acq(&g_cnt[S1]) : 0u;
        unsigned c2 = (NSEG > 2) ? ld_acq(&g_cnt[S2]) : 0u;

        // ---- seg0: poll + stage + commit ----
        {
            const unsigned tgt = ncta_of(S0) * ut;
            if (c0 < tgt) while (ld_acq(&g_cnt[S0]) < tgt) __nanosleep(60);
            const float4* sp = (const float4*)(hb + ((S0 << 9) + (W0 & 511)) * 16);
            #pragma unroll
            for (int i = 0; i < L0 / 64; i++)
                cp16(sHb + (unsigned)(i * NTHR + tid) * 16u, sp + i * NTHR + tid);
            CP_COMMIT();
        }
        if constexpr (NSEG > 1) {
            const unsigned tgt = ncta_of(S1) * ut;
            if (c1 < tgt) while (ld_acq(&g_cnt[S1]) < tgt) __nanosleep(60);
            const float4* sp = (const float4*)(hb + ((S1 << 9) + (W1 & 511)) * 16);
            const unsigned dst = sHb + (unsigned)L0 * 64u;
            #pragma unroll
            for (int i = 0; i < L1 / 64; i++)
                cp16(dst + (unsigned)(i * NTHR + tid) * 16u, sp + i * NTHR + tid);
            CP_COMMIT();
        }
        if constexpr (NSEG > 2) {
            const unsigned tgt = ncta_of(S2) * ut;
            if (c2 < tgt) while (ld_acq(&g_cnt[S2]) < tgt) __nanosleep(60);
            const float4* sp = (const float4*)(hb + ((S2 << 9) + (W2 & 511)) * 16);
            const unsigned dst = sHb + (unsigned)(L0 + L1) * 64u;
            #pragma unroll
            for (int i = 0; i < L2 / 64; i++)
                cp16(dst + (unsigned)(i * NTHR + tid) * 16u, sp + i * NTHR + tid);
            CP_COMMIT();
        }
        if (RG == 0 && tid < 64)
            sInp[tid] = __ldg(inp + (size_t)(tid >> 2) * TT * 4 + t * 4 + (tid & 3));

        // ---- compute, segment-by-segment (staging overlaps compute) ----
        unsigned long long a[8] = {0, 0, 0, 0, 0, 0, 0, 0};
        const ulonglong2* sH2 = (const ulonglong2*)sH;

        if constexpr (NSEG == 3) CP_WAIT(2); else if constexpr (NSEG == 2) CP_WAIT(1); else CP_WAIT(0);
        __syncthreads();
        if (act) dot_seg<R>(sWt, sH2, jt, 0, klo0, khi0, a);

        if constexpr (NSEG > 1) {
            if constexpr (NSEG == 3) CP_WAIT(1); else CP_WAIT(0);
            __syncthreads();
            if (act) dot_seg<R>(sWt, sH2, jt, L0, klo1, khi1, a);
        }
        if constexpr (NSEG > 2) {
            CP_WAIT(0);
            __syncthreads();
            if (act) dot_seg<R>(sWt, sH2, jt, L0 + L1, klo2, khi2, a);
        }

        // ---- store partials ----
        if (act) {
            ulonglong2* rp = (ulonglong2*)sRed + ((size_t)s * R + jt) * 4;
            rp[0] = make_ulonglong2(a[0], a[1]); rp[1] = make_ulonglong2(a[2], a[3]);
            rp[2] = make_ulonglong2(a[4], a[5]); rp[3] = make_ulonglong2(a[6], a[7]);
        }
        __syncthreads();

        // ---- reduce across S + state update ----
        if (upd) {
            unsigned long long x = 0, y = 0;
            const ulonglong2* rp = (const ulonglong2*)sRed + (size_t)jr * 4 + q;
            #pragma unroll
            for (int ss = 0; ss < S; ss++) {
                ulonglong2 v = rp[(size_t)ss * R * 4];
                ADD2(x, v.x); ADD2(y, v.y);
            }
            float ac[4];
            UNPK2(ac[0], ac[1], x); UNPK2(ac[2], ac[3], y);
            float w0 = 0.f, w1 = 0.f, w2 = 0.f, w3 = 0.f;
            if (RG == 0) { w0 = sWi[jr*4]; w1 = sWi[jr*4+1]; w2 = sWi[jr*4+2]; w3 = sWi[jr*4+3]; }
            float* hp = &hown.x;
            #pragma unroll
            for (int i2 = 0; i2 < 4; i2++) {
                const int b = q * 4 + i2;
                float d = sInh[jr * 16 + b] + tonic;
                if (RG == 0)
                    d += w0 * sInp[b*4] + w1 * sInp[b*4+1] + w2 * sInp[b*4+2] + w3 * sInp[b*4+3];
                float v = hp[i2] * (1.f - DTC) + DTC * (ac[i2] + d);
                v = fmaxf(v, 0.f);
                hp[i2] = v;
                d_out[RNN_OFF + ((size_t)b * TT + t) * H6 + jg_u] = v;
                if (t == TT - 1) d_out[HN_OFF + (size_t)b * H6 + jg_u] = v;
            }
            __stcg((float4*)(g_h[(t + 1) & 7] + (size_t)jg_u * 16) + q, hown);
            __threadfence();   // make h + counter ordering airtight across threads
        }
        __syncthreads();
        if (tid == 0) red_rel(&g_cnt[RG]);   // publish step t done (release)
    }
}

__global__ void __launch_bounds__(NTHR, 1) rnn_persist(
    const float* __restrict__ inp, const float* __restrict__ inhib,
    const float* __restrict__ inp_w, float* __restrict__ d_out)
{
    extern __shared__ float sm[];
    const int b = blockIdx.x;
    //                  RG  R   S    K  NSEG  S0  W0   L0  S1  W1   L1  S2  W2    L2
    if (b < 32) {       // str rows 128..383 (str + thal + alm)
        run_region<0,  8, 32, 1408, 3,  0, 0, 512,  4, 512, 512,  5, 1024, 384>(
            128 + b * 8, inp, inhib, inp_w, d_out, sm);
    } else if (b < 48) { // str rows 0..127 & 384..511 (str + alm)
        int c = b - 32;
        int j0 = (c < 8) ? c * 16 : 384 + (c - 8) * 16;
        run_region<0, 16, 16,  896, 2,  0, 0, 512,  5, 1024, 384,  0, 0, 0>(
            j0, inp, inhib, inp_w, d_out, sm);
    } else if (b < 56) { // gpe (str[256:512])
        run_region<1, 64,  4,  256, 1,  0, 256, 256,  0, 0, 0,  0, 0, 0>(
            (b - 48) * 64, inp, inhib, inp_w, d_out, sm);
    } else if (b < 72) { // stn (gpe)
        run_region<2, 32,  8,  512, 1,  1, 0, 512,  0, 0, 0,  0, 0, 0>(
            (b - 56) * 32, inp, inhib, inp_w, d_out, sm);
    } else if (b < 100) { // snr (str[0:256] + stn)
        run_region<3, 19, 13,  768, 2,  0, 0, 256,  2, 512, 512,  0, 0, 0>(
            (b - 72) * 19, inp, inhib, inp_w, d_out, sm);
    } else if (b < 116) { // thal (snr)
        run_region<4, 32,  8,  512, 1,  3, 0, 512,  0, 0, 0,  0, 0, 0>(
            (b - 100) * 32, inp, inhib, inp_w, d_out, sm);
    } else {             // alm (thal + alm)
        run_region<5, 16, 16, 1024, 2,  4, 0, 512,  5, 512, 512,  0, 0, 0>(
            (b - 116) * 16, inp, inhib, inp_w, d_out, sm);
    }
}

// ---------------- epilogue: out = sigmoid(alm_h . v) ---------------------
__global__ void out_kernel(float* __restrict__ d_out)
{
    int gw   = (blockIdx.x * blockDim.x + threadIdx.x) >> 5;
    int lane = threadIdx.x & 31;
    if (gw >= BB * TT) return;
    const float* row = d_out + RNN_OFF + (size_t)gw * H6 + 5 * HID;
    float sum = 0.f;
    for (int j = lane; j < HID; j += 32) sum = fmaf(row[j], g_v[j], sum);
    #pragma unroll
    for (int o = 16; o; o >>= 1) sum += __shfl_xor_sync(0xffffffffu, sum, o);
    if (lane == 0) d_out[gw] = 1.f / (1.f + expf(-sum));
}

// ---------------- epilogue: x_out / x_last broadcast copy ----------------
__global__ void x_kernel(const float* __restrict__ x, float* __restrict__ d_out)
{
    const float4* x4 = (const float4*)x;
    float4* o4 = (float4*)d_out;
    const size_t total = 12288 + 12288000;
    for (size_t i = blockIdx.x * (size_t)blockDim.x + threadIdx.x; i < total;
         i += (size_t)gridDim.x * blockDim.x) {
        if (i < 12288) {
            o4[XLAST_OFF / 4 + i] = x4[i];
        } else {
            size_t e = i - 12288;
            int j4 = (int)(e % 768);
            int bt = (int)(e / 768);
            int bq = bt / TT;
            o4[XOUT_OFF / 4 + e] = x4[bq * 768 + j4];
        }
    }
}

extern "C" void kernel_launch(void* const* d_in, const int* in_sizes, int n_in,
                              void* d_out_v, int out_size)
{
    const float* inp        = (const float*)d_in[0];
    const float* hn         = (const float*)d_in[1];
    const float* x          = (const float*)d_in[2];
    const float* inhib      = (const float*)d_in[3];
    const float* thal2alm_w = (const float*)d_in[5];
    const float* thal2str_w = (const float*)d_in[6];
    const float* alm2alm_w  = (const float*)d_in[7];
    const float* alm2str_w  = (const float*)d_in[8];
    const float* str2snr_w  = (const float*)d_in[9];
    const float* str2gpe_w  = (const float*)d_in[10];
    const float* gpe2stn_w  = (const float*)d_in[11];
    const float* stn2snr_w  = (const float*)d_in[12];
    const float* snr2thal_w = (const float*)d_in[13];
    const float* inp_w      = (const float*)d_in[14];
    const float* fc1        = (const float*)d_in[15];
    const float* fc2        = (const float*)d_in[16];
    const float* fixed      = (const float*)d_in[17];
    float* d_out = (float*)d_out_v;

    // max smem: r0A = 45056 + 90112 + 32768 + 512 + 128 + 256 = 168832 B
    static int smem_set = 0;
    if (!smem_set) {
        cudaFuncSetAttribute(rnn_persist, cudaFuncAttributeMaxDynamicSharedMemorySize, 172032);
        smem_set = 1;
    }

    // x_kernel first: independent of the RNN, overlaps prep
    x_kernel<<<4096, NTHR>>>(x, d_out);

    int prep_total = W_TOT + H6 * BB + HID;
    prep_kernel<<<(prep_total + NTHR - 1) / NTHR, NTHR>>>(
        hn, thal2alm_w, thal2str_w, alm2alm_w, alm2str_w, str2snr_w,
        str2gpe_w, gpe2stn_w, stn2snr_w, snr2thal_w, fc1, fc2, fixed);

    rnn_persist<<<NCTA, NTHR, 172032>>>(inp, inhib, inp_w, d_out);

    out_kernel<<<(BB * TT * 32 + NTHR - 1) / NTHR, NTHR>>>(d_out);
}

// round 8
// speedup vs baseline: 2.5638x; 1.0351x over previous
#include <cuda_runtime.h>
#include <cstdint>

#define HID 512
#define H6  3072
#define BB  16
#define TT  1000
#define DTC 0.01f
#define NTHR 256
#define NCTA 148

#define W_TOT 2621440
// output layout (floats): out | hn_last | rnn_out | x_last | x_out
#define OUT_OFF   0ULL
#define HN_OFF    16000ULL
#define RNN_OFF   65152ULL
#define XLAST_OFF 49217152ULL
#define XOUT_OFF  49266304ULL

// -------- persistent device state ----------
__device__ __align__(16) float g_Wt[W_TOT];      // packed effective W, per region [Kcat][512]
__device__ __align__(16) float g_h[8][H6 * BB];  // h ring buffer, layout [j][b]
__device__ float g_v[HID];                       // relu(fc1[alm]) @ relu(fc2)
__device__ unsigned g_cnt[768];                  // per-region counters, 512B apart (idx r*128)

__host__ __device__ constexpr int roff_of(int r) {
    return r==0?0 : r==1?786432 : r==2?1048576 : r==3?1310720 : r==4?1835008 : 2097152;
}
// CTAs per region: str=48, gpe=8, stn=16, snr=28, thal=16, alm=32
__host__ __device__ constexpr unsigned ncta_of(int r) {
    return r==0?48u : r==1?8u : r==2?16u : r==3?28u : r==4?16u : 32u;
}

// ---------------- PTX helpers ----------------
__device__ __forceinline__ void cp16(unsigned dst_s, const void* src) {
    asm volatile("cp.async.cg.shared.global [%0], [%1], 16;" :: "r"(dst_s), "l"(src) : "memory");
}
#define CP_COMMIT() asm volatile("cp.async.commit_group;" ::: "memory")
#define CP_WAIT(N)  asm volatile("cp.async.wait_group %0;" :: "n"(N) : "memory")
__device__ __forceinline__ unsigned ld_acq(const unsigned* p) {
    unsigned v;
    asm volatile("ld.acquire.gpu.global.u32 %0, [%1];" : "=r"(v) : "l"(p) : "memory");
    return v;
}
__device__ __forceinline__ void red_rel(unsigned* p) {
    asm volatile("red.release.gpu.global.add.u32 [%0], %1;" :: "l"(p), "r"(1u) : "memory");
}
#define FMA2(acc, w, h) asm("fma.rn.f32x2 %0, %1, %2, %0;" : "+l"(acc) : "l"(w), "l"(h))
#define ADD2(acc, v)    asm("add.rn.f32x2 %0, %0, %1;"     : "+l"(acc) : "l"(v))
#define PACK2(d, f)     asm("mov.b64 %0, {%1, %1};"        : "=l"(d)   : "f"(f))
#define UNPK2(lo, hi, v) asm("mov.b64 {%0, %1}, %2;" : "=f"(lo), "=f"(hi) : "l"(v))

// ---------------- prep: build W_eff, init h0, v, reset counters ----------
__global__ void prep_kernel(
    const float* __restrict__ hn,
    const float* __restrict__ thal2alm_w, const float* __restrict__ thal2str_w,
    const float* __restrict__ alm2alm_w,  const float* __restrict__ alm2str_w,
    const float* __restrict__ str2snr_w,  const float* __restrict__ str2gpe_w,
    const float* __restrict__ gpe2stn_w,  const float* __restrict__ stn2snr_w,
    const float* __restrict__ snr2thal_w, const float* __restrict__ fc1,
    const float* __restrict__ fc2,        const float* __restrict__ str2str_fixed)
{
    int idx = blockIdx.x * blockDim.x + threadIdx.x;
    if (idx < 768) g_cnt[idx] = 0u;
    if (idx < W_TOT) {
        int r;
        if (idx < 786432) r = 0;
        else if (idx < 1048576) r = 1;
        else if (idx < 1310720) r = 2;
        else if (idx < 1835008) r = 3;
        else if (idx < 2097152) r = 4;
        else r = 5;
        int rem  = idx - roff_of(r);
        int kcat = rem >> 9;
        int j    = rem & 511;
        int seg  = kcat >> 9;
        int k    = kcat & 511;
        int wi = j * HID + k;
        float val;
        if (r == 0) {
            if (seg == 0)      val = -str2str_fixed[wi];
            else if (seg == 1) val = (j >= 128 && j < 384) ? fmaxf(thal2str_w[wi], 0.f) : 0.f;
            else               val = (k < 359) ? fmaxf(alm2str_w[wi], 0.f) : 0.f;
        } else if (r == 1) {
            val = (k >= 256) ? -fmaxf(str2gpe_w[wi], 0.f) : 0.f;
        } else if (r == 2) {
            val = -fmaxf(gpe2stn_w[wi], 0.f);
        } else if (r == 3) {
            val = (seg == 0) ? ((k < 256) ? -fmaxf(str2snr_w[wi], 0.f) : 0.f)
                             : fmaxf(stn2snr_w[wi], 0.f);
        } else if (r == 4) {
            val = -fmaxf(snr2thal_w[wi], 0.f);
        } else {
            val = (seg == 0) ? fmaxf(thal2alm_w[wi], 0.f)
                             : fmaxf(alm2alm_w[wi], 0.f) * ((k < 359) ? 1.f : -1.f);
        }
        g_Wt[idx] = val;
    } else if (idx < W_TOT + H6 * BB) {
        int e = idx - W_TOT;
        int j = e >> 4, b = e & 15;
        g_h[0][e] = hn[b * H6 + j];
    } else if (idx < W_TOT + H6 * BB + HID) {
        int j = idx - (W_TOT + H6 * BB);
        const float* f1 = fc1 + (size_t)(5 * HID + j) * HID;
        float s = 0.f;
        for (int m = 0; m < HID; m++) s += fmaxf(f1[m], 0.f) * fmaxf(fc2[m], 0.f);
        g_v[j] = s;
    }
}

// ---------------- inner dot-product over one segment ---------------------
template<int R>
__device__ __forceinline__ void dot_seg(const float* __restrict__ sWt,
    const ulonglong2* __restrict__ sH2, int jt, int coff, int klo, int khi,
    unsigned long long* a)
{
    const float* pw = sWt + (size_t)(coff + klo) * R + jt;
    const ulonglong2* ph = sH2 + (size_t)(coff + klo) * 4;
    #pragma unroll 4
    for (int k = klo; k < khi; k++) {
        float w = *pw; pw += R;
        unsigned long long ww; PACK2(ww, w);
        ulonglong2 u0 = ph[0], u1 = ph[1], u2 = ph[2], u3 = ph[3]; ph += 4;
        FMA2(a[0], ww, u0.x); FMA2(a[1], ww, u0.y);
        FMA2(a[2], ww, u1.x); FMA2(a[3], ww, u1.y);
        FMA2(a[4], ww, u2.x); FMA2(a[5], ww, u2.y);
        FMA2(a[6], ww, u3.x); FMA2(a[7], ww, u3.y);
    }
}

// ---------------- persistent recurrence, templated per region ------------
// Segments: (SRC region, W orig-kcat offset, L length). h rows = SRC*512 + (W&511) + k
template<int RG, int R, int S, int K, int NSEG,
         int S0, int W0, int L0, int S1, int W1, int L1, int S2, int W2, int L2>
__device__ __forceinline__ void run_region(
    int j0, const float* __restrict__ inp, const float* __restrict__ inhib,
    const float* __restrict__ inp_w, float* __restrict__ d_out, float* sm)
{
    const int tid = threadIdx.x;

    float* sWt  = sm;                      // K*R  [k][jj]
    float* sH   = sWt + K * R;             // K*16 [k][b]
    float* sRed = sH + K * 16;             // S*R*16
    float* sInh = sRed + S * R * 16;       // R*16
    float* sWi  = sInh + R * 16;           // R*4
    float* sInp = sWi + R * 4;             // 64

    // ---- one-time weight fills (per segment, concat layout) ----
    for (int i = tid; i < L0 * R; i += NTHR) {
        int k = i / R, jj = i - k * R; int jrow = j0 + jj;
        sWt[(size_t)k * R + jj] = (jrow < 512) ? g_Wt[roff_of(RG) + ((W0 + k) << 9) + jrow] : 0.f;
    }
    if constexpr (NSEG > 1)
    for (int i = tid; i < L1 * R; i += NTHR) {
        int k = i / R, jj = i - k * R; int jrow = j0 + jj;
        sWt[(size_t)(L0 + k) * R + jj] = (jrow < 512) ? g_Wt[roff_of(RG) + ((W1 + k) << 9) + jrow] : 0.f;
    }
    if constexpr (NSEG > 2)
    for (int i = tid; i < L2 * R; i += NTHR) {
        int k = i / R, jj = i - k * R; int jrow = j0 + jj;
        sWt[(size_t)(L0 + L1 + k) * R + jj] = (jrow < 512) ? g_Wt[roff_of(RG) + ((W2 + k) << 9) + jrow] : 0.f;
    }
    for (int i = tid; i < R * 16; i += NTHR) {
        int jj = i >> 4, b = i & 15; int jrow = j0 + jj;
        sInh[i] = (jrow < 512) ? inhib[b * H6 + RG * HID + jrow] : 0.f;
    }
    for (int i = tid; i < R * 4; i += NTHR) {
        int jj = i >> 2, ii = i & 3; int jrow = j0 + jj;
        int jg = RG * HID + jrow;
        float st = (RG == 0 && jrow < 512 && jg >= 128 && jg < 384) ? 1.f : 0.f;
        sWi[i] = st * fmaxf(inp_w[ii * H6 + (jg < H6 ? jg : 0)], 0.f);
    }
    const float tonic = (RG == 1 || RG == 2 || RG == 4) ? 1.f : 0.f;

    // ---- update-thread identity + h kept in registers ----
    const int jr = tid >> 2, q = tid & 3;
    const int jrow_u = j0 + jr;
    const bool upd = (tid < 4 * R) && (jrow_u < 512);
    const int jg_u = RG * HID + jrow_u;
    float4 hown = make_float4(0.f, 0.f, 0.f, 0.f);
    if (upd) hown = *((const float4*)(g_h[0] + (size_t)jg_u * 16) + q);

    const unsigned sHb = (unsigned)__cvta_generic_to_shared(sH);
    const int jt = tid % R;
    const int s  = tid / R;
    const bool act = s < S;
    const int klo0 = (s * L0) / S,        khi0 = ((s + 1) * L0) / S;
    const int klo1 = (s * L1) / S,        khi1 = ((s + 1) * L1) / S;
    const int klo2 = (s * L2) / S,        khi2 = ((s + 1) * L2) / S;

    __syncthreads();

    for (int t = 0; t < TT; t++) {
        const float* hb = g_h[t & 7];
        const unsigned ut = (unsigned)t;

        // ---- inp staging first: independent of counters ----
        if (RG == 0 && tid < 64)
            sInp[tid] = __ldg(inp + (size_t)(tid >> 2) * TT * 4 + t * 4 + (tid & 3));

        // ---- parallel first-read of source counters ----
        unsigned c0 = ld_acq(&g_cnt[S0 * 128]);
        unsigned c1 = (NSEG > 1) ? ld_acq(&g_cnt[S1 * 128]) : 0u;
        unsigned c2 = (NSEG > 2) ? ld_acq(&g_cnt[S2 * 128]) : 0u;

        // ---- seg0: poll + stage + commit ----
        {
            const unsigned tgt = ncta_of(S0) * ut;
            if (c0 < tgt) while (ld_acq(&g_cnt[S0 * 128]) < tgt) __nanosleep(40);
            const float4* sp = (const float4*)(hb + ((S0 << 9) + (W0 & 511)) * 16);
            #pragma unroll
            for (int i = 0; i < L0 / 64; i++)
                cp16(sHb + (unsigned)(i * NTHR + tid) * 16u, sp + i * NTHR + tid);
            CP_COMMIT();
        }
        if constexpr (NSEG > 1) {
            const unsigned tgt = ncta_of(S1) * ut;
            if (c1 < tgt) while (ld_acq(&g_cnt[S1 * 128]) < tgt) __nanosleep(40);
            const float4* sp = (const float4*)(hb + ((S1 << 9) + (W1 & 511)) * 16);
            const unsigned dst = sHb + (unsigned)L0 * 64u;
            #pragma unroll
            for (int i = 0; i < L1 / 64; i++)
                cp16(dst + (unsigned)(i * NTHR + tid) * 16u, sp + i * NTHR + tid);
            CP_COMMIT();
        }
        if constexpr (NSEG > 2) {
            const unsigned tgt = ncta_of(S2) * ut;
            if (c2 < tgt) while (ld_acq(&g_cnt[S2 * 128]) < tgt) __nanosleep(40);
            const float4* sp = (const float4*)(hb + ((S2 << 9) + (W2 & 511)) * 16);
            const unsigned dst = sHb + (unsigned)(L0 + L1) * 64u;
            #pragma unroll
            for (int i = 0; i < L2 / 64; i++)
                cp16(dst + (unsigned)(i * NTHR + tid) * 16u, sp + i * NTHR + tid);
            CP_COMMIT();
        }

        // ---- compute, segment-by-segment (staging overlaps compute) ----
        unsigned long long a[8] = {0, 0, 0, 0, 0, 0, 0, 0};
        const ulonglong2* sH2 = (const ulonglong2*)sH;

        if constexpr (NSEG == 3) CP_WAIT(2); else if constexpr (NSEG == 2) CP_WAIT(1); else CP_WAIT(0);
        __syncthreads();
        if (act) dot_seg<R>(sWt, sH2, jt, 0, klo0, khi0, a);

        if constexpr (NSEG > 1) {
            if constexpr (NSEG == 3) CP_WAIT(1); else CP_WAIT(0);
            __syncthreads();
            if (act) dot_seg<R>(sWt, sH2, jt, L0, klo1, khi1, a);
        }
        if constexpr (NSEG > 2) {
            CP_WAIT(0);
            __syncthreads();
            if (act) dot_seg<R>(sWt, sH2, jt, L0 + L1, klo2, khi2, a);
        }

        // ---- store partials ----
        if (act) {
            ulonglong2* rp = (ulonglong2*)sRed + ((size_t)s * R + jt) * 4;
            rp[0] = make_ulonglong2(a[0], a[1]); rp[1] = make_ulonglong2(a[2], a[3]);
            rp[2] = make_ulonglong2(a[4], a[5]); rp[3] = make_ulonglong2(a[6], a[7]);
        }
        __syncthreads();

        // ---- reduce across S + state update (h only; d_out deferred) ----
        if (upd) {
            unsigned long long x0 = 0, x1 = 0, y0 = 0, y1 = 0;
            const ulonglong2* rp = (const ulonglong2*)sRed + (size_t)jr * 4 + q;
            #pragma unroll
            for (int ss = 0; ss + 1 < S; ss += 2) {
                ulonglong2 v0 = rp[(size_t)ss * R * 4];
                ulonglong2 v1 = rp[(size_t)(ss + 1) * R * 4];
                ADD2(x0, v0.x); ADD2(y0, v0.y);
                ADD2(x1, v1.x); ADD2(y1, v1.y);
            }
            if constexpr (S & 1) {
                ulonglong2 v0 = rp[(size_t)(S - 1) * R * 4];
                ADD2(x0, v0.x); ADD2(y0, v0.y);
            }
            ADD2(x0, x1); ADD2(y0, y1);
            float ac[4];
            UNPK2(ac[0], ac[1], x0); UNPK2(ac[2], ac[3], y0);
            float w0 = 0.f, w1 = 0.f, w2 = 0.f, w3 = 0.f;
            if (RG == 0) { w0 = sWi[jr*4]; w1 = sWi[jr*4+1]; w2 = sWi[jr*4+2]; w3 = sWi[jr*4+3]; }
            float* hp = &hown.x;
            #pragma unroll
            for (int i2 = 0; i2 < 4; i2++) {
                const int b = q * 4 + i2;
                float d = sInh[jr * 16 + b] + tonic;
                if (RG == 0)
                    d += w0 * sInp[b*4] + w1 * sInp[b*4+1] + w2 * sInp[b*4+2] + w3 * sInp[b*4+3];
                float v = hp[i2] * (1.f - DTC) + DTC * (ac[i2] + d);
                hp[i2] = fmaxf(v, 0.f);
            }
            __stcg((float4*)(g_h[(t + 1) & 7] + (size_t)jg_u * 16) + q, hown);
        }
        __syncthreads();
        // single fence + publish: syncthreads gives intra-CTA HB; cumulative
        // gpu-scope fence + release RED extends it to consumer CTAs
        if (tid == 0) { __threadfence(); red_rel(&g_cnt[RG * 128]); }

        // ---- deferred d_out writes: off the inter-region critical path ----
        if (upd) {
            const float* hp = &hown.x;
            #pragma unroll
            for (int i2 = 0; i2 < 4; i2++) {
                const int b = q * 4 + i2;
                d_out[RNN_OFF + ((size_t)b * TT + t) * H6 + jg_u] = hp[i2];
                if (t == TT - 1) d_out[HN_OFF + (size_t)b * H6 + jg_u] = hp[i2];
            }
        }
    }
}

__global__ void __launch_bounds__(NTHR, 1) rnn_persist(
    const float* __restrict__ inp, const float* __restrict__ inhib,
    const float* __restrict__ inp_w, float* __restrict__ d_out)
{
    extern __shared__ float sm[];
    const int b = blockIdx.x;
    //                  RG  R   S    K  NSEG  S0  W0   L0  S1  W1   L1  S2  W2    L2
    if (b < 32) {       // str rows 128..383 (str + thal + alm)
        run_region<0,  8, 32, 1408, 3,  0, 0, 512,  4, 512, 512,  5, 1024, 384>(
            128 + b * 8, inp, inhib, inp_w, d_out, sm);
    } else if (b < 48) { // str rows 0..127 & 384..511 (str + alm)
        int c = b - 32;
        int j0 = (c < 8) ? c * 16 : 384 + (c - 8) * 16;
        run_region<0, 16, 16,  896, 2,  0, 0, 512,  5, 1024, 384,  0, 0, 0>(
            j0, inp, inhib, inp_w, d_out, sm);
    } else if (b < 56) { // gpe (str[256:512])
        run_region<1, 64,  4,  256, 1,  0, 256, 256,  0, 0, 0,  0, 0, 0>(
            (b - 48) * 64, inp, inhib, inp_w, d_out, sm);
    } else if (b < 72) { // stn (gpe)
        run_region<2, 32,  8,  512, 1,  1, 0, 512,  0, 0, 0,  0, 0, 0>(
            (b - 56) * 32, inp, inhib, inp_w, d_out, sm);
    } else if (b < 100) { // snr (str[0:256] + stn)
        run_region<3, 19, 13,  768, 2,  0, 0, 256,  2, 512, 512,  0, 0, 0>(
            (b - 72) * 19, inp, inhib, inp_w, d_out, sm);
    } else if (b < 116) { // thal (snr)
        run_region<4, 32,  8,  512, 1,  3, 0, 512,  0, 0, 0,  0, 0, 0>(
            (b - 100) * 32, inp, inhib, inp_w, d_out, sm);
    } else {             // alm (thal + alm)
        run_region<5, 16, 16, 1024, 2,  4, 0, 512,  5, 512, 512,  0, 0, 0>(
            (b - 116) * 16, inp, inhib, inp_w, d_out, sm);
    }
}

// ---------------- epilogue: out = sigmoid(alm_h . v) ---------------------
__global__ void out_kernel(float* __restrict__ d_out)
{
    int gw   = (blockIdx.x * blockDim.x + threadIdx.x) >> 5;
    int lane = threadIdx.x & 31;
    if (gw >= BB * TT) return;
    const float4* row4 = (const float4*)(d_out + RNN_OFF + (size_t)gw * H6 + 5 * HID);
    const float4* v4   = (const float4*)g_v;
    float sum = 0.f;
    #pragma unroll
    for (int j = lane; j < 128; j += 32) {
        float4 rv = row4[j], vv = v4[j];
        sum = fmaf(rv.x, vv.x, fmaf(rv.y, vv.y, fmaf(rv.z, vv.z, fmaf(rv.w, vv.w, sum))));
    }
    #pragma unroll
    for (int o = 16; o; o >>= 1) sum += __shfl_xor_sync(0xffffffffu, sum, o);
    if (lane == 0) d_out[gw] = 1.f / (1.f + expf(-sum));
}

// ---------------- epilogue: x_out / x_last broadcast copy ----------------
__global__ void x_kernel(const float* __restrict__ x, float* __restrict__ d_out)
{
    const float4* x4 = (const float4*)x;
    float4* o4 = (float4*)d_out;
    const size_t total = 12288 + 12288000;
    for (size_t i = blockIdx.x * (size_t)blockDim.x + threadIdx.x; i < total;
         i += (size_t)gridDim.x * blockDim.x) {
        if (i < 12288) {
            o4[XLAST_OFF / 4 + i] = x4[i];
        } else {
            size_t e = i - 12288;
            int j4 = (int)(e % 768);
            int bt = (int)(e / 768);
            int bq = bt / TT;
            o4[XOUT_OFF / 4 + e] = x4[bq * 768 + j4];
        }
    }
}

extern "C" void kernel_launch(void* const* d_in, const int* in_sizes, int n_in,
                              void* d_out_v, int out_size)
{
    const float* inp        = (const float*)d_in[0];
    const float* hn         = (const float*)d_in[1];
    const float* x          = (const float*)d_in[2];
    const float* inhib      = (const float*)d_in[3];
    const float* thal2alm_w = (const float*)d_in[5];
    const float* thal2str_w = (const float*)d_in[6];
    const float* alm2alm_w  = (const float*)d_in[7];
    const float* alm2str_w  = (const float*)d_in[8];
    const float* str2snr_w  = (const float*)d_in[9];
    const float* str2gpe_w  = (const float*)d_in[10];
    const float* gpe2stn_w  = (const float*)d_in[11];
    const float* stn2snr_w  = (const float*)d_in[12];
    const float* snr2thal_w = (const float*)d_in[13];
    const float* inp_w      = (const float*)d_in[14];
    const float* fc1        = (const float*)d_in[15];
    const float* fc2        = (const float*)d_in[16];
    const float* fixed      = (const float*)d_in[17];
    float* d_out = (float*)d_out_v;

    static int smem_set = 0;
    if (!smem_set) {
        cudaFuncSetAttribute(rnn_persist, cudaFuncAttributeMaxDynamicSharedMemorySize, 172032);
        smem_set = 1;
    }

    // x_kernel first: independent of the RNN, overlaps prep
    x_kernel<<<4096, NTHR>>>(x, d_out);

    int prep_total = W_TOT + H6 * BB + HID;
    prep_kernel<<<(prep_total + NTHR - 1) / NTHR, NTHR>>>(
        hn, thal2alm_w, thal2str_w, alm2alm_w, alm2str_w, str2snr_w,
        str2gpe_w, gpe2stn_w, stn2snr_w, snr2thal_w, fc1, fc2, fixed);

    rnn_persist<<<NCTA, NTHR, 172032>>>(inp, inhib, inp_w, d_out);

    out_kernel<<<(BB * TT * 32 + NTHR - 1) / NTHR, NTHR>>>(d_out);
}